// round 8
// baseline (speedup 1.0000x reference)
#include <cuda_runtime.h>
#include <cuda_bf16.h>
#include <cstdint>

// Problem constants
#define BB 8
#define NN 2048
#define KNN 16
#define NPTS (BB * NN)            // 16384
#define NEDGE (NPTS * KNN)        // 262144

// Static scratch (allocation-free rule)
__device__ float g_X0[NPTS * 256];
__device__ float g_X1[NPTS * 256];
__device__ float g_sqn[NPTS];
__device__ float g_S[(long long)BB * NN * NN];     // 134 MB distance scores
__device__ int   g_idx[NEDGE];
__device__ float g_PQ[NPTS * 1024];                // 64 MB  [P | Q] per node
__device__ float g_Wcat[256 * 1024];               // [Wd | W1b]
__device__ float g_bcat[1024];

// packed fp32x2 helpers (sm_100+: FFMA2 via PTX fma.rn.f32x2)
__device__ __forceinline__ unsigned long long pack2(float x)
{
    unsigned long long r;
    asm("mov.b64 %0, {%1, %1};" : "=l"(r) : "f"(x));
    return r;
}
__device__ __forceinline__ void fma2(unsigned long long& d, unsigned long long a,
                                     unsigned long long b)
{
    asm("fma.rn.f32x2 %0, %1, %2, %0;" : "+l"(d) : "l"(a), "l"(b));
}
__device__ __forceinline__ void unpack2(float& lo, float& hi, unsigned long long v)
{
    asm("mov.b64 {%0, %1}, %2;" : "=f"(lo), "=f"(hi) : "l"(v));
}

// ---------------------------------------------------------------------------
// Generic 64x64 register-tiled SGEMM, FFMA2 inner loop (exact fp32).
// epi: 0 = (+bias if bias!=null), 2 = dist: C = -2*acc + sqn[n]
// transB: 0 -> B[k*ldb+n], 1 -> B[n*ldb+k]
// ---------------------------------------------------------------------------
__global__ __launch_bounds__(256)
void sgemm64(const float* __restrict__ A, const float* __restrict__ B,
             const float* __restrict__ bias, const float* __restrict__ sqn,
             float* __restrict__ C,
             int M, int Nn, int Kd,
             int lda, int ldb, int ldc,
             int transB, int epi,
             long long sA, long long sB, long long sC, int sSqn)
{
    int bz = blockIdx.z;
    A += bz * sA;
    B += bz * sB;
    C += bz * sC;
    const float* sq = sqn ? (sqn + (long long)bz * sSqn) : nullptr;

    __shared__ __align__(16) float As[16][68];
    __shared__ __align__(16) float Bs[16][68];

    int t = threadIdx.x;
    int tx = t & 15, ty = t >> 4;
    int bm = blockIdx.y * 64, bn = blockIdx.x * 64;

    unsigned long long acc2[4][2];
#pragma unroll
    for (int i = 0; i < 4; i++)
#pragma unroll
        for (int j = 0; j < 2; j++) acc2[i][j] = 0ull;

    for (int kt = 0; kt < Kd; kt += 16) {
#pragma unroll
        for (int e = t; e < 1024; e += 256) {
            int m = e >> 4, k = e & 15;
            int gm = bm + m, gk = kt + k;
            As[k][m] = (gm < M && gk < Kd) ? A[(long long)gm * lda + gk] : 0.f;
        }
        if (!transB) {
#pragma unroll
            for (int e = t; e < 1024; e += 256) {
                int k = e >> 6, n = e & 63;
                int gk = kt + k, gn = bn + n;
                Bs[k][n] = (gk < Kd && gn < Nn) ? B[(long long)gk * ldb + gn] : 0.f;
            }
        } else {
#pragma unroll
            for (int e = t; e < 1024; e += 256) {
                int n = e >> 4, k = e & 15;
                int gk = kt + k, gn = bn + n;
                Bs[k][n] = (gk < Kd && gn < Nn) ? B[(long long)gn * ldb + gk] : 0.f;
            }
        }
        __syncthreads();
#pragma unroll
        for (int k = 0; k < 16; k++) {
            unsigned long long bb[2];
            bb[0] = *reinterpret_cast<const unsigned long long*>(&Bs[k][tx * 4]);
            bb[1] = *reinterpret_cast<const unsigned long long*>(&Bs[k][tx * 4 + 2]);
#pragma unroll
            for (int i = 0; i < 4; i++) {
                unsigned long long aa = pack2(As[k][ty * 4 + i]);
                fma2(acc2[i][0], aa, bb[0]);
                fma2(acc2[i][1], aa, bb[1]);
            }
        }
        __syncthreads();
    }

#pragma unroll
    for (int i = 0; i < 4; i++) {
        int gm = bm + ty * 4 + i;
        if (gm >= M) continue;
        float v4[4];
        unpack2(v4[0], v4[1], acc2[i][0]);
        unpack2(v4[2], v4[3], acc2[i][1]);
#pragma unroll
        for (int j = 0; j < 4; j++) {
            int gn = bn + tx * 4 + j;
            if (gn >= Nn) continue;
            float v = v4[j];
            if (epi == 2) {
                v = -2.f * v + sq[gn];
            } else {
                if (bias) v += bias[gn];
            }
            C[(long long)gm * ldc + gn] = v;
        }
    }
}

// ---------------------------------------------------------------------------
// squared norms, one warp per row
// ---------------------------------------------------------------------------
__global__ void sqnorm_kernel(const float* __restrict__ X, float* __restrict__ sqn, int D)
{
    int warp = (blockIdx.x * blockDim.x + threadIdx.x) >> 5;
    int lane = threadIdx.x & 31;
    if (warp >= NPTS) return;
    const float* row = X + (long long)warp * D;
    float s = 0.f;
    for (int c = lane; c < D; c += 32) { float v = row[c]; s += v * v; }
#pragma unroll
    for (int off = 16; off; off >>= 1) s += __shfl_xor_sync(0xffffffffu, s, off);
    if (lane == 0) sqn[warp] = s;
}

// ---------------------------------------------------------------------------
// top-16 smallest per row (warp per row, 4 rows/block, iterative selection)
// ---------------------------------------------------------------------------
__global__ __launch_bounds__(128)
void topk_kernel(const float* __restrict__ S, int* __restrict__ idx)
{
    __shared__ float sm[4][NN];
    int warp = threadIdx.x >> 5, lane = threadIdx.x & 31;
    int r = blockIdx.x * 4 + warp;
    const float* row = S + (long long)r * NN;
    for (int j = lane; j < NN; j += 32) sm[warp][j] = row[j];
    __syncwarp();

    unsigned long long used = 0ull;
    for (int it = 0; it < KNN; it++) {
        float best = 3.4e38f;
        int bidx = 1 << 30;
#pragma unroll 8
        for (int tt = 0; tt < 64; tt++) {
            if (!((used >> tt) & 1ull)) {
                int j = lane + (tt << 5);
                float v = sm[warp][j];
                if (v < best || (v == best && j < bidx)) { best = v; bidx = j; }
            }
        }
#pragma unroll
        for (int off = 16; off; off >>= 1) {
            float ov = __shfl_xor_sync(0xffffffffu, best, off);
            int oi = __shfl_xor_sync(0xffffffffu, bidx, off);
            if (ov < best || (ov == best && oi < bidx)) { best = ov; bidx = oi; }
        }
        if ((bidx & 31) == lane) used |= 1ull << (bidx >> 5);
        if (lane == 0) idx[r * KNN + it] = bidx;
    }
}

// ---------------------------------------------------------------------------
// Wcat = [W1a - W1b | W1b]  (din x 2c2);  bcat = [b1 | 0]
// ---------------------------------------------------------------------------
__global__ void prep_kernel(const float* __restrict__ W1, const float* __restrict__ b1,
                            float* __restrict__ Wcat, float* __restrict__ bcat,
                            int din, int c2)
{
    int i = blockIdx.x * blockDim.x + threadIdx.x;
    int ld = 2 * c2;
    int total = din * ld;
    if (i < total) {
        int r = i / ld, c = i % ld;
        float v;
        if (c < c2) v = W1[r * c2 + c] - W1[(din + r) * c2 + c];
        else        v = W1[(din + r) * c2 + (c - c2)];
        Wcat[i] = v;
    }
    if (i < ld) bcat[i] = (i < c2) ? b1[i] : 0.f;
}

// ---------------------------------------------------------------------------
// Fused edge kernel (FFMA2, exact fp32):
//   edge e=(i,j): a_e = relu(P_i + Q_j)   generated in A-tile fill
//   H2_e = relu(a_e @ W2 + b2)            FFMA2 inner loop
//   Xout[node] = mean over the node's 16 edges   fused in epilogue
// Block: 64 edges (= 4 complete nodes) x 64 output cols, 256 threads.
// Thread (tx,ty): rows ty*4..ty*4+3 (all in node ty>>2), cols tx*4..tx*4+3.
// ---------------------------------------------------------------------------
__global__ __launch_bounds__(256)
void edge_ffma2_kernel(const float* __restrict__ PQ, const int* __restrict__ idx,
                       const float* __restrict__ W2, const float* __restrict__ b2,
                       float* __restrict__ Xout, int c2, int dout)
{
    __shared__ __align__(16) float As[16][68];
    __shared__ __align__(16) float Bs[16][68];
    __shared__ float Red[16][68];
    __shared__ int   poff[64], qoff[64];
    __shared__ float bs2[64];

    int t = threadIdx.x;
    int tx = t & 15, ty = t >> 4;
    int bn = blockIdx.x * 64;
    int be = blockIdx.y * 64;
    int ld = 2 * c2;

    if (t < 64) {
        int e = be + t;
        int r = e >> 4;
        int b = r >> 11;
        int j = idx[e];
        poff[t] = r * ld;
        qoff[t] = ((b << 11) + j) * ld + c2;
        int gn = bn + t;
        bs2[t] = (gn < dout) ? b2[gn] : 0.f;
    }
    __syncthreads();

    unsigned long long acc2[4][2];
#pragma unroll
    for (int i = 0; i < 4; i++)
#pragma unroll
        for (int j = 0; j < 2; j++) acc2[i][j] = 0ull;

    for (int kt = 0; kt < c2; kt += 16) {
        // A tile 64x16: relu(P_i + Q_j)
#pragma unroll
        for (int e = t; e < 1024; e += 256) {
            int m = e >> 4, k = e & 15;
            As[k][m] = fmaxf(PQ[poff[m] + kt + k] + PQ[qoff[m] + kt + k], 0.f);
        }
        // B tile 16x64 from W2 [c2 x dout]
#pragma unroll
        for (int e = t; e < 1024; e += 256) {
            int k = e >> 6, n = e & 63;
            int gn = bn + n;
            Bs[k][n] = (gn < dout) ? W2[(kt + k) * dout + gn] : 0.f;
        }
        __syncthreads();
#pragma unroll
        for (int k = 0; k < 16; k++) {
            unsigned long long bb[2];
            bb[0] = *reinterpret_cast<const unsigned long long*>(&Bs[k][tx * 4]);
            bb[1] = *reinterpret_cast<const unsigned long long*>(&Bs[k][tx * 4 + 2]);
#pragma unroll
            for (int i = 0; i < 4; i++) {
                unsigned long long aa = pack2(As[k][ty * 4 + i]);
                fma2(acc2[i][0], aa, bb[0]);
                fma2(acc2[i][1], aa, bb[1]);
            }
        }
        __syncthreads();
    }

    // per-edge bias + relu, then partial sum over this thread's 4 rows (same node)
    float part[4] = {0.f, 0.f, 0.f, 0.f};
#pragma unroll
    for (int i = 0; i < 4; i++) {
        float v4[4];
        unpack2(v4[0], v4[1], acc2[i][0]);
        unpack2(v4[2], v4[3], acc2[i][1]);
#pragma unroll
        for (int j = 0; j < 4; j++)
            part[j] += fmaxf(v4[j] + bs2[tx * 4 + j], 0.f);
    }
#pragma unroll
    for (int j = 0; j < 4; j++) Red[ty][tx * 4 + j] = part[j];
    __syncthreads();

    // combine 4 ty-groups per node (16 rows) -> mean -> Xout
    {
        int nd = t >> 6, c = t & 63;
        int gn = bn + c;
        if (gn < dout) {
            float s = Red[nd * 4 + 0][c] + Red[nd * 4 + 1][c]
                    + Red[nd * 4 + 2][c] + Red[nd * 4 + 3][c];
            int node = blockIdx.y * 4 + nd;
            Xout[(long long)node * dout + gn] = s * (1.f / 16.f);
        }
    }
}

// ---------------------------------------------------------------------------
// global mean pool + final linear -> [8,2]
// ---------------------------------------------------------------------------
__global__ void final_kernel(const float* __restrict__ X, const float* __restrict__ Wf,
                             const float* __restrict__ bf, float* __restrict__ out)
{
    __shared__ float pooled[BB][16];
    int t = threadIdx.x;
    if (t < 128) {
        int b = t >> 4, c = t & 15;
        float s = 0.f;
        const float* base = X + ((long long)b * NN) * 16 + c;
        for (int n = 0; n < NN; n++) s += base[n * 16];
        pooled[b][c] = s / (float)NN;
    }
    __syncthreads();
    if (t < 16) {
        int b = t >> 1, o = t & 1;
        float s = bf[o];
#pragma unroll
        for (int c = 0; c < 16; c++) s += pooled[b][c] * Wf[c * 2 + o];
        out[b * 2 + o] = s;
    }
}

// ---------------------------------------------------------------------------
extern "C" void kernel_launch(void* const* d_in, const int* in_sizes, int n_in,
                              void* d_out, int out_size)
{
    (void)in_sizes; (void)n_in; (void)out_size;
    static const int DIMS[7] = {3, 32, 128, 256, 64, 32, 16};

    float *X0, *X1, *S, *PQ, *Wcat, *bcat, *sqn;
    int* idxp;
    cudaGetSymbolAddress((void**)&X0,   g_X0);
    cudaGetSymbolAddress((void**)&X1,   g_X1);
    cudaGetSymbolAddress((void**)&S,    g_S);
    cudaGetSymbolAddress((void**)&PQ,   g_PQ);
    cudaGetSymbolAddress((void**)&Wcat, g_Wcat);
    cudaGetSymbolAddress((void**)&bcat, g_bcat);
    cudaGetSymbolAddress((void**)&sqn,  g_sqn);
    cudaGetSymbolAddress((void**)&idxp, g_idx);

    const float* cur = (const float*)d_in[0];

    for (int l = 0; l < 6; l++) {
        int din = DIMS[l], dout = DIMS[l + 1], c2 = 2 * dout;
        const float* W1 = (const float*)d_in[1 + 4 * l];
        const float* b1 = (const float*)d_in[2 + 4 * l];
        const float* W2 = (const float*)d_in[3 + 4 * l];
        const float* b2 = (const float*)d_in[4 + 4 * l];
        float* Xn = (l & 1) ? X1 : X0;

        // 1) squared norms
        sqnorm_kernel<<<NPTS * 32 / 256, 256>>>(cur, sqn, din);

        // 2) distance scores S = -2*X X^T + ||x_j||^2  (batched over B, fp32)
        sgemm64<<<dim3(NN / 64, NN / 64, BB), 256>>>(
            cur, cur, nullptr, sqn, S,
            NN, NN, din, din, din, NN,
            /*transB=*/1, /*epi=*/2,
            (long long)NN * din, (long long)NN * din, (long long)NN * NN, NN);

        // 3) top-16 neighbor indices
        topk_kernel<<<NPTS / 4, 128>>>(S, idxp);

        // 4) Wcat = [W1a-W1b | W1b], bcat = [b1 | 0]
        prep_kernel<<<(din * 2 * c2 + 255) / 256, 256>>>(W1, b1, Wcat, bcat, din, c2);

        // 5) PQ = X @ Wcat + bcat   -> [NPTS, 2c2] = [P | Q]
        sgemm64<<<dim3((2 * c2 + 63) / 64, NPTS / 64, 1), 256>>>(
            cur, Wcat, bcat, nullptr, PQ,
            NPTS, 2 * c2, din, din, 2 * c2, 2 * c2, 0, 0, 0, 0, 0, 0);

        // 6) fused: H1 gen + GEMM2 (FFMA2) + bias/relu + k-mean
        edge_ffma2_kernel<<<dim3((dout + 63) / 64, NEDGE / 64), 256>>>(
            PQ, idxp, W2, b2, Xn, c2, dout);

        cur = Xn;
    }

    final_kernel<<<1, 128>>>(cur, (const float*)d_in[25], (const float*)d_in[26],
                             (float*)d_out);
}

// round 10
// speedup vs baseline: 1.6900x; 1.6900x over previous
#include <cuda_runtime.h>
#include <cuda_bf16.h>
#include <cstdint>

// Problem constants
#define BB 8
#define NN 2048
#define KNN 16
#define NPTS (BB * NN)            // 16384
#define NEDGE (NPTS * KNN)        // 262144

// Static scratch (allocation-free rule)
__device__ float g_X0[NPTS * 256];
__device__ float g_X1[NPTS * 256];
__device__ float g_sqn[NPTS];
__device__ float g_S[(long long)BB * NN * NN];     // 134 MB distance scores
__device__ int   g_idx[NEDGE];
__device__ float g_PQ[NPTS * 1024];                // 64 MB  [P | Q] per node
__device__ float g_Wcat[256 * 1024];               // [Wd | W1b]
__device__ float g_bcat[1024];

// packed fp32x2 helpers (sm_100+: FFMA2 via PTX fma.rn.f32x2)
__device__ __forceinline__ unsigned long long pack2(float x)
{
    unsigned long long r;
    asm("mov.b64 %0, {%1, %1};" : "=l"(r) : "f"(x));
    return r;
}
__device__ __forceinline__ void fma2(unsigned long long& d, unsigned long long a,
                                     unsigned long long b)
{
    asm("fma.rn.f32x2 %0, %1, %2, %0;" : "+l"(d) : "l"(a), "l"(b));
}
__device__ __forceinline__ void unpack2(float& lo, float& hi, unsigned long long v)
{
    asm("mov.b64 {%0, %1}, %2;" : "=f"(lo), "=f"(hi) : "l"(v));
}

// ---------------------------------------------------------------------------
// Generic 64x64 register-tiled SGEMM, FFMA2 inner loop, 2-stage pipeline.
// epi: 0 = (+bias if bias!=null), 2 = dist: C = -2*acc + sqn[n]
// transB: 0 -> B[k*ldb+n], 1 -> B[n*ldb+k]
// ---------------------------------------------------------------------------
__global__ __launch_bounds__(256)
void sgemm64(const float* __restrict__ A, const float* __restrict__ B,
             const float* __restrict__ bias, const float* __restrict__ sqn,
             float* __restrict__ C,
             int M, int Nn, int Kd,
             int lda, int ldb, int ldc,
             int transB, int epi,
             long long sA, long long sB, long long sC, int sSqn)
{
    int bz = blockIdx.z;
    A += bz * sA;
    B += bz * sB;
    C += bz * sC;
    const float* sq = sqn ? (sqn + (long long)bz * sSqn) : nullptr;

    __shared__ __align__(16) float As[16][68];
    __shared__ __align__(16) float Bs[16][68];

    int t = threadIdx.x;
    int tx = t & 15, ty = t >> 4;
    int bm = blockIdx.y * 64, bn = blockIdx.x * 64;

    unsigned long long acc2[4][2];
#pragma unroll
    for (int i = 0; i < 4; i++)
#pragma unroll
        for (int j = 0; j < 2; j++) acc2[i][j] = 0ull;

    float ra[4], rb[4];

    // element coordinates for this thread's 4 fill elements
    // A: e = t + i*256 -> m=e>>4, k=e&15   (As[k][m])
    // B: e = t + i*256 -> (notrans) k=e>>6,n=e&63 ; (trans) n=e>>4,k=e&15

#define SG_LOAD(KT)                                                            \
    {                                                                          \
        int kt_ = (KT);                                                        \
        _Pragma("unroll")                                                      \
        for (int i = 0; i < 4; i++) {                                          \
            int e = t + i * 256;                                               \
            int m = e >> 4, k = e & 15;                                        \
            int gm = bm + m, gk = kt_ + k;                                     \
            ra[i] = (gm < M && gk < Kd) ? A[(long long)gm * lda + gk] : 0.f;   \
        }                                                                      \
        if (!transB) {                                                         \
            _Pragma("unroll")                                                  \
            for (int i = 0; i < 4; i++) {                                      \
                int e = t + i * 256;                                           \
                int k = e >> 6, n = e & 63;                                    \
                int gk = kt_ + k, gn = bn + n;                                 \
                rb[i] = (gk < Kd && gn < Nn) ? B[(long long)gk * ldb + gn] : 0.f; \
            }                                                                  \
        } else {                                                               \
            _Pragma("unroll")                                                  \
            for (int i = 0; i < 4; i++) {                                      \
                int e = t + i * 256;                                           \
                int n = e >> 4, k = e & 15;                                    \
                int gk = kt_ + k, gn = bn + n;                                 \
                rb[i] = (gk < Kd && gn < Nn) ? B[(long long)gn * ldb + gk] : 0.f; \
            }                                                                  \
        }                                                                      \
    }

    SG_LOAD(0);

    for (int kt = 0; kt < Kd; kt += 16) {
        // store staged regs -> smem
#pragma unroll
        for (int i = 0; i < 4; i++) {
            int e = t + i * 256;
            As[e & 15][e >> 4] = ra[i];
        }
        if (!transB) {
#pragma unroll
            for (int i = 0; i < 4; i++) {
                int e = t + i * 256;
                Bs[e >> 6][e & 63] = rb[i];
            }
        } else {
#pragma unroll
            for (int i = 0; i < 4; i++) {
                int e = t + i * 256;
                Bs[e & 15][e >> 4] = rb[i];
            }
        }
        __syncthreads();

        // prefetch next tile (latency overlaps compute below)
        if (kt + 16 < Kd) SG_LOAD(kt + 16);

#pragma unroll
        for (int k = 0; k < 16; k++) {
            unsigned long long bb[2];
            bb[0] = *reinterpret_cast<const unsigned long long*>(&Bs[k][tx * 4]);
            bb[1] = *reinterpret_cast<const unsigned long long*>(&Bs[k][tx * 4 + 2]);
#pragma unroll
            for (int i = 0; i < 4; i++) {
                unsigned long long aa = pack2(As[k][ty * 4 + i]);
                fma2(acc2[i][0], aa, bb[0]);
                fma2(acc2[i][1], aa, bb[1]);
            }
        }
        __syncthreads();
    }
#undef SG_LOAD

#pragma unroll
    for (int i = 0; i < 4; i++) {
        int gm = bm + ty * 4 + i;
        if (gm >= M) continue;
        float v4[4];
        unpack2(v4[0], v4[1], acc2[i][0]);
        unpack2(v4[2], v4[3], acc2[i][1]);
#pragma unroll
        for (int j = 0; j < 4; j++) {
            int gn = bn + tx * 4 + j;
            if (gn >= Nn) continue;
            float v = v4[j];
            if (epi == 2) {
                v = -2.f * v + sq[gn];
            } else {
                if (bias) v += bias[gn];
            }
            C[(long long)gm * ldc + gn] = v;
        }
    }
}

// ---------------------------------------------------------------------------
// squared norms, one warp per row
// ---------------------------------------------------------------------------
__global__ void sqnorm_kernel(const float* __restrict__ X, float* __restrict__ sqn, int D)
{
    int warp = (blockIdx.x * blockDim.x + threadIdx.x) >> 5;
    int lane = threadIdx.x & 31;
    if (warp >= NPTS) return;
    const float* row = X + (long long)warp * D;
    float s = 0.f;
    for (int c = lane; c < D; c += 32) { float v = row[c]; s += v * v; }
#pragma unroll
    for (int off = 16; off; off >>= 1) s += __shfl_xor_sync(0xffffffffu, s, off);
    if (lane == 0) sqn[warp] = s;
}

// ---------------------------------------------------------------------------
// top-16 smallest per row (warp per row, 4 rows/block, iterative selection)
// ---------------------------------------------------------------------------
__global__ __launch_bounds__(128)
void topk_kernel(const float* __restrict__ S, int* __restrict__ idx)
{
    __shared__ float sm[4][NN];
    int warp = threadIdx.x >> 5, lane = threadIdx.x & 31;
    int r = blockIdx.x * 4 + warp;
    const float* row = S + (long long)r * NN;
    for (int j = lane; j < NN; j += 32) sm[warp][j] = row[j];
    __syncwarp();

    unsigned long long used = 0ull;
    for (int it = 0; it < KNN; it++) {
        float best = 3.4e38f;
        int bidx = 1 << 30;
#pragma unroll 8
        for (int tt = 0; tt < 64; tt++) {
            if (!((used >> tt) & 1ull)) {
                int j = lane + (tt << 5);
                float v = sm[warp][j];
                if (v < best || (v == best && j < bidx)) { best = v; bidx = j; }
            }
        }
#pragma unroll
        for (int off = 16; off; off >>= 1) {
            float ov = __shfl_xor_sync(0xffffffffu, best, off);
            int oi = __shfl_xor_sync(0xffffffffu, bidx, off);
            if (ov < best || (ov == best && oi < bidx)) { best = ov; bidx = oi; }
        }
        if ((bidx & 31) == lane) used |= 1ull << (bidx >> 5);
        if (lane == 0) idx[r * KNN + it] = bidx;
    }
}

// ---------------------------------------------------------------------------
// Wcat = [W1a - W1b | W1b]  (din x 2c2);  bcat = [b1 | 0]
// ---------------------------------------------------------------------------
__global__ void prep_kernel(const float* __restrict__ W1, const float* __restrict__ b1,
                            float* __restrict__ Wcat, float* __restrict__ bcat,
                            int din, int c2)
{
    int i = blockIdx.x * blockDim.x + threadIdx.x;
    int ld = 2 * c2;
    int total = din * ld;
    if (i < total) {
        int r = i / ld, c = i % ld;
        float v;
        if (c < c2) v = W1[r * c2 + c] - W1[(din + r) * c2 + c];
        else        v = W1[(din + r) * c2 + (c - c2)];
        Wcat[i] = v;
    }
    if (i < ld) bcat[i] = (i < c2) ? b1[i] : 0.f;
}

// ---------------------------------------------------------------------------
// Fused edge kernel (FFMA2, exact fp32, 2-stage pipelined):
//   edge e=(i,j): a_e = relu(P_i + Q_j)   generated in A-tile fill
//   H2_e = relu(a_e @ W2 + b2)            FFMA2 inner loop
//   Xout[node] = mean over the node's 16 edges   fused in epilogue
// Block: 64 edges (= 4 complete nodes) x 64 output cols, 256 threads.
// ---------------------------------------------------------------------------
__global__ __launch_bounds__(256)
void edge_ffma2_kernel(const float* __restrict__ PQ, const int* __restrict__ idx,
                       const float* __restrict__ W2, const float* __restrict__ b2,
                       float* __restrict__ Xout, int c2, int dout)
{
    __shared__ __align__(16) float As[16][68];
    __shared__ __align__(16) float Bs[16][68];
    __shared__ float Red[16][68];
    __shared__ int   poff[64], qoff[64];
    __shared__ float bs2[64];

    int t = threadIdx.x;
    int tx = t & 15, ty = t >> 4;
    int bn = blockIdx.x * 64;
    int be = blockIdx.y * 64;
    int ld = 2 * c2;

    if (t < 64) {
        int e = be + t;
        int r = e >> 4;
        int b = r >> 11;
        int j = idx[e];
        poff[t] = r * ld;
        qoff[t] = ((b << 11) + j) * ld + c2;
        int gn = bn + t;
        bs2[t] = (gn < dout) ? b2[gn] : 0.f;
    }
    __syncthreads();

    unsigned long long acc2[4][2];
#pragma unroll
    for (int i = 0; i < 4; i++)
#pragma unroll
        for (int j = 0; j < 2; j++) acc2[i][j] = 0ull;

    // this thread's fixed fill coordinates
    int am[4], ak[4];
#pragma unroll
    for (int i = 0; i < 4; i++) {
        int e = t + i * 256;
        am[i] = e >> 4;
        ak[i] = e & 15;
    }

    float pa[4], qa[4], rbw[4];

#define EG_LOAD(KT)                                                            \
    {                                                                          \
        int kt_ = (KT);                                                        \
        _Pragma("unroll")                                                      \
        for (int i = 0; i < 4; i++) {                                          \
            pa[i] = PQ[poff[am[i]] + kt_ + ak[i]];                             \
            qa[i] = PQ[qoff[am[i]] + kt_ + ak[i]];                             \
        }                                                                      \
        _Pragma("unroll")                                                      \
        for (int i = 0; i < 4; i++) {                                          \
            int e = t + i * 256;                                               \
            int k = e >> 6, n = e & 63;                                        \
            int gn = bn + n;                                                   \
            rbw[i] = (gn < dout) ? W2[(kt_ + k) * dout + gn] : 0.f;            \
        }                                                                      \
    }

    EG_LOAD(0);

    for (int kt = 0; kt < c2; kt += 16) {
#pragma unroll
        for (int i = 0; i < 4; i++)
            As[ak[i]][am[i]] = fmaxf(pa[i] + qa[i], 0.f);
#pragma unroll
        for (int i = 0; i < 4; i++) {
            int e = t + i * 256;
            Bs[e >> 6][e & 63] = rbw[i];
        }
        __syncthreads();

        if (kt + 16 < c2) EG_LOAD(kt + 16);

#pragma unroll
        for (int k = 0; k < 16; k++) {
            unsigned long long bb[2];
            bb[0] = *reinterpret_cast<const unsigned long long*>(&Bs[k][tx * 4]);
            bb[1] = *reinterpret_cast<const unsigned long long*>(&Bs[k][tx * 4 + 2]);
#pragma unroll
            for (int i = 0; i < 4; i++) {
                unsigned long long aa = pack2(As[k][ty * 4 + i]);
                fma2(acc2[i][0], aa, bb[0]);
                fma2(acc2[i][1], aa, bb[1]);
            }
        }
        __syncthreads();
    }
#undef EG_LOAD

    // per-edge bias + relu, then partial sum over this thread's 4 rows (same node)
    float part[4] = {0.f, 0.f, 0.f, 0.f};
#pragma unroll
    for (int i = 0; i < 4; i++) {
        float v4[4];
        unpack2(v4[0], v4[1], acc2[i][0]);
        unpack2(v4[2], v4[3], acc2[i][1]);
#pragma unroll
        for (int j = 0; j < 4; j++)
            part[j] += fmaxf(v4[j] + bs2[tx * 4 + j], 0.f);
    }
#pragma unroll
    for (int j = 0; j < 4; j++) Red[ty][tx * 4 + j] = part[j];
    __syncthreads();

    // combine 4 ty-groups per node (16 rows) -> mean -> Xout
    {
        int nd = t >> 6, c = t & 63;
        int gn = bn + c;
        if (gn < dout) {
            float s = Red[nd * 4 + 0][c] + Red[nd * 4 + 1][c]
                    + Red[nd * 4 + 2][c] + Red[nd * 4 + 3][c];
            int node = blockIdx.y * 4 + nd;
            Xout[(long long)node * dout + gn] = s * (1.f / 16.f);
        }
    }
}

// ---------------------------------------------------------------------------
// global mean pool + final linear -> [8,2]
// ---------------------------------------------------------------------------
__global__ void final_kernel(const float* __restrict__ X, const float* __restrict__ Wf,
                             const float* __restrict__ bf, float* __restrict__ out)
{
    __shared__ float pooled[BB][16];
    int t = threadIdx.x;
    if (t < 128) {
        int b = t >> 4, c = t & 15;
        float s = 0.f;
        const float* base = X + ((long long)b * NN) * 16 + c;
        for (int n = 0; n < NN; n++) s += base[n * 16];
        pooled[b][c] = s / (float)NN;
    }
    __syncthreads();
    if (t < 16) {
        int b = t >> 1, o = t & 1;
        float s = bf[o];
#pragma unroll
        for (int c = 0; c < 16; c++) s += pooled[b][c] * Wf[c * 2 + o];
        out[b * 2 + o] = s;
    }
}

// ---------------------------------------------------------------------------
extern "C" void kernel_launch(void* const* d_in, const int* in_sizes, int n_in,
                              void* d_out, int out_size)
{
    (void)in_sizes; (void)n_in; (void)out_size;
    static const int DIMS[7] = {3, 32, 128, 256, 64, 32, 16};

    float *X0, *X1, *S, *PQ, *Wcat, *bcat, *sqn;
    int* idxp;
    cudaGetSymbolAddress((void**)&X0,   g_X0);
    cudaGetSymbolAddress((void**)&X1,   g_X1);
    cudaGetSymbolAddress((void**)&S,    g_S);
    cudaGetSymbolAddress((void**)&PQ,   g_PQ);
    cudaGetSymbolAddress((void**)&Wcat, g_Wcat);
    cudaGetSymbolAddress((void**)&bcat, g_bcat);
    cudaGetSymbolAddress((void**)&sqn,  g_sqn);
    cudaGetSymbolAddress((void**)&idxp, g_idx);

    const float* cur = (const float*)d_in[0];

    for (int l = 0; l < 6; l++) {
        int din = DIMS[l], dout = DIMS[l + 1], c2 = 2 * dout;
        const float* W1 = (const float*)d_in[1 + 4 * l];
        const float* b1 = (const float*)d_in[2 + 4 * l];
        const float* W2 = (const float*)d_in[3 + 4 * l];
        const float* b2 = (const float*)d_in[4 + 4 * l];
        float* Xn = (l & 1) ? X1 : X0;

        // 1) squared norms
        sqnorm_kernel<<<NPTS * 32 / 256, 256>>>(cur, sqn, din);

        // 2) distance scores S = -2*X X^T + ||x_j||^2  (batched over B, fp32)
        sgemm64<<<dim3(NN / 64, NN / 64, BB), 256>>>(
            cur, cur, nullptr, sqn, S,
            NN, NN, din, din, din, NN,
            /*transB=*/1, /*epi=*/2,
            (long long)NN * din, (long long)NN * din, (long long)NN * NN, NN);

        // 3) top-16 neighbor indices
        topk_kernel<<<NPTS / 4, 128>>>(S, idxp);

        // 4) Wcat = [W1a-W1b | W1b], bcat = [b1 | 0]
        prep_kernel<<<(din * 2 * c2 + 255) / 256, 256>>>(W1, b1, Wcat, bcat, din, c2);

        // 5) PQ = X @ Wcat + bcat   -> [NPTS, 2c2] = [P | Q]
        sgemm64<<<dim3((2 * c2 + 63) / 64, NPTS / 64, 1), 256>>>(
            cur, Wcat, bcat, nullptr, PQ,
            NPTS, 2 * c2, din, din, 2 * c2, 2 * c2, 0, 0, 0, 0, 0, 0);

        // 6) fused: H1 gen + GEMM2 (FFMA2, pipelined) + bias/relu + k-mean
        edge_ffma2_kernel<<<dim3((dout + 63) / 64, NEDGE / 64), 256>>>(
            PQ, idxp, W2, b2, Xn, c2, dout);

        cur = Xn;
    }

    final_kernel<<<1, 128>>>(cur, (const float*)d_in[25], (const float*)d_in[26],
                             (float*)d_out);
}